// round 16
// baseline (speedup 1.0000x reference)
#include <cuda_runtime.h>
#include <cuda_fp16.h>
#include <cuda_bf16.h>
#include <math.h>
#include <stdint.h>

#define BATCH  64
#define EMBED  512
#define HID    1024
#define G4     4096
#define VOCAB  50257
#define TSTEPS 18
#define MROWS  (BATCH*TSTEPS)   // 1152
#define KDIM   1024
#define PCTA   128              // persistent LSTM CTAs
#define CCTA   20               // converter CTAs (idle SMs)

// ---------------- device scratch (static device globals; no allocs) ---------
__device__ float g_gate_base[BATCH * G4];            // [b][p]  (permuted rows)
__device__ float g_c[BATCH * HID];                   // [b][j]
__device__ int   g_bar[TSTEPS];                      // grid-barrier counters
__device__ __nv_bfloat16 g_hhi[BATCH * HID];         // h hi [b][j]
__device__ __nv_bfloat16 g_hlo[BATCH * HID];         // h lo
__device__ __nv_bfloat16 g_whh_hi[G4 * KDIM];        // permuted rows, 8 MB
__device__ __nv_bfloat16 g_whh_lo[G4 * KDIM];        // 8 MB
__device__ __half g_Ah[MROWS * KDIM];                // vocab A fp16  2.3 MB
__device__ __half g_Whi[(size_t)VOCAB * KDIM];       // 103 MB

// permuted row: r = gi*HID + j  ->  p = (j>>3)*32 + gi*8 + (j&7)
__device__ __forceinline__ int perm_row(int r) {
    int gi = r >> 10, j = r & (HID - 1);
    return ((j >> 3) << 5) + (gi << 3) + (j & 7);
}

// ---------------------------------------------------------------- helpers ---
__device__ __forceinline__ uint32_t smem_u32(const void* p) {
    uint32_t a;
    asm("{ .reg .u64 t; cvta.to.shared.u64 t, %1; cvt.u32.u64 %0, t; }"
        : "=r"(a) : "l"(p));
    return a;
}
__device__ __forceinline__ void cp16(uint32_t s, const void* g) {
    asm volatile("cp.async.cg.shared.global [%0], [%1], 16;" :: "r"(s), "l"(g) : "memory");
}
__device__ __forceinline__ void cp_commit() {
    asm volatile("cp.async.commit_group;" ::: "memory");
}
__device__ __forceinline__ void cp_wait1() {
    asm volatile("cp.async.wait_group 1;" ::: "memory");
}
__device__ __forceinline__ void cp_wait0() {
    asm volatile("cp.async.wait_group 0;" ::: "memory");
}
__device__ __forceinline__ void ldsm4(uint32_t* r, uint32_t a) {
    asm volatile("ldmatrix.sync.aligned.m8n8.x4.shared.b16 {%0,%1,%2,%3}, [%4];"
                 : "=r"(r[0]), "=r"(r[1]), "=r"(r[2]), "=r"(r[3]) : "r"(a));
}
__device__ __forceinline__ void mma_fp16(float* c, const uint32_t* a, const uint32_t* b) {
    asm volatile(
        "mma.sync.aligned.m16n8k16.row.col.f32.f16.f16.f32 "
        "{%0,%1,%2,%3},{%4,%5,%6,%7},{%8,%9},{%0,%1,%2,%3};"
        : "+f"(c[0]), "+f"(c[1]), "+f"(c[2]), "+f"(c[3])
        : "r"(a[0]), "r"(a[1]), "r"(a[2]), "r"(a[3]), "r"(b[0]), "r"(b[1]));
}
__device__ __forceinline__ void mma_bf16(float* c, const uint32_t* a, const uint32_t* b) {
    asm volatile(
        "mma.sync.aligned.m16n8k16.row.col.f32.bf16.bf16.f32 "
        "{%0,%1,%2,%3},{%4,%5,%6,%7},{%8,%9},{%0,%1,%2,%3};"
        : "+f"(c[0]), "+f"(c[1]), "+f"(c[2]), "+f"(c[3])
        : "r"(a[0]), "r"(a[1]), "r"(a[2]), "r"(a[3]), "r"(b[0]), "r"(b[1]));
}

// ---------------------------------------------------------------- init ------
__global__ void init_kernel() {
    int i = blockIdx.x * blockDim.x + threadIdx.x;
    if (i < BATCH * HID) {
        g_c[i] = 0.f;
        g_hhi[i] = __float2bfloat16(0.f);
        g_hlo[i] = __float2bfloat16(0.f);
    }
    if (i < TSTEPS) g_bar[i] = 0;
}

// --------------------------------- x_proj -> gate_base[b][perm(r)] ----------
__global__ void xproj_kernel(const float4* __restrict__ feat4,
                             const float4* __restrict__ wih4,
                             const float*  __restrict__ b_ih,
                             const float*  __restrict__ b_hh) {
    __shared__ float4 fs[BATCH * 32];
    int tid = threadIdx.x;
    int rl  = tid & 31;
    int bg  = tid >> 5;
    int r   = blockIdx.x * 32 + rl;
    float acc[8];
#pragma unroll
    for (int j = 0; j < 8; j++) acc[j] = 0.f;
    for (int ec = 0; ec < 4; ec++) {
        __syncthreads();
#pragma unroll
        for (int i = 0; i < 8; i++) {
            int lin = i * 256 + tid;
            int b = lin >> 5, q = lin & 31;
            fs[lin] = feat4[b * 128 + ec * 32 + q];
        }
        __syncthreads();
#pragma unroll 4
        for (int eq = 0; eq < 32; eq++) {
            float4 w = wih4[r * 128 + ec * 32 + eq];
#pragma unroll
            for (int jj = 0; jj < 8; jj++) {
                float4 f = fs[(bg * 8 + jj) * 32 + eq];
                acc[jj] += w.x * f.x + w.y * f.y + w.z * f.z + w.w * f.w;
            }
        }
    }
    float bias = b_ih[r] + b_hh[r];
    int p = perm_row(r);
#pragma unroll
    for (int jj = 0; jj < 8; jj++)
        g_gate_base[(bg * 8 + jj) * G4 + p] = acc[jj] + bias;
}

// ----------------------- W_hh fp32 -> bf16 hi/lo, permuted rows -------------
__global__ void convWhh_kernel(const float4* __restrict__ w) {
    int r = blockIdx.x;              // source row 0..4095
    int q = threadIdx.x;             // 0..255
    float4 v = w[(size_t)r * 256 + q];
    float x[4] = {v.x, v.y, v.z, v.w};
    __nv_bfloat16 hi[4], lo[4];
#pragma unroll
    for (int j = 0; j < 4; j++) {
        hi[j] = __float2bfloat16_rn(x[j]);
        lo[j] = __float2bfloat16_rn(x[j] - __bfloat162float(hi[j]));
    }
    uint32_t h01 = ((uint32_t)__bfloat16_as_ushort(hi[1]) << 16) | __bfloat16_as_ushort(hi[0]);
    uint32_t h23 = ((uint32_t)__bfloat16_as_ushort(hi[3]) << 16) | __bfloat16_as_ushort(hi[2]);
    uint32_t l01 = ((uint32_t)__bfloat16_as_ushort(lo[1]) << 16) | __bfloat16_as_ushort(lo[0]);
    uint32_t l23 = ((uint32_t)__bfloat16_as_ushort(lo[3]) << 16) | __bfloat16_as_ushort(lo[2]);
    int p = perm_row(r);
    ((uint2*)(g_whh_hi + (size_t)p * KDIM))[q] = make_uint2(h01, h23);
    ((uint2*)(g_whh_lo + (size_t)p * KDIM))[q] = make_uint2(l01, l23);
}

// -------------------- persistent LSTM: 18 steps, 1 launch -------------------
// Grid 148: CTAs [0,128) run the LSTM (grid barrier over 128); CTAs [128,148)
// are converter CTAs on otherwise-idle SMs, streaming W_fc fp32 -> fp16 in the
// LSTM's shadow. GEMM launches after (stream order) so conversion is done.
#define BPITCH  2064                  // 1024k*2B + 16
#define B_RES   (32 * BPITCH)         // 66048 per half
#define AOFF    (2 * B_RES)           // 132096
#define APITCH2 144                   // 64k*2B + 16
#define A_HALF  (64 * APITCH2)        // 9216
#define A_STG   (2 * A_HALF)          // hi+lo 18432 (per group per stage)
#define P_SMEM  (AOFF + 4 * A_STG)    // 205824
#define GPITCH  34                    // EVEN: float2 stores stay 8B-aligned

__device__ __forceinline__ void loadA_step(uint32_t sbase, int stage, int it,
                                           int tid) {
#pragma unroll
    for (int r = 0; r < 8; r++) {          // 2048 cp16: 2 groups x (hi+lo)
        int f = r * 256 + tid;
        int g = f >> 10, q = f & 1023;
        int half = q >> 9, q2 = q & 511;
        int row = q2 >> 3, qq = q2 & 7;
        int k0 = g * 512 + it * 64;
        const __nv_bfloat16* src = half ? g_hlo : g_hhi;
        cp16(sbase + AOFF + (uint32_t)(stage * 2 + g) * A_STG
             + (uint32_t)(half * A_HALF + row * APITCH2 + qq * 16),
             src + (size_t)row * KDIM + k0 + qq * 8);
    }
}

__global__ void __launch_bounds__(256)
lstm_persist(const float4* __restrict__ wfc) {
    // ---------------- converter CTAs: W_fc fp32 -> fp16 ----------------
    if (blockIdx.x >= PCTA) {
        const size_t total = (size_t)VOCAB * 256;          // float4 count
        int c = blockIdx.x - PCTA;                          // 0..CCTA-1
        const size_t stride = (size_t)CCTA * 256;
        uint2* dst = (uint2*)g_Whi;
        for (size_t i = (size_t)c * 256 + threadIdx.x; i < total;
             i += 4 * stride) {
            float4 v[4];
            bool ok[4];
#pragma unroll
            for (int j = 0; j < 4; j++) {
                size_t idx = i + (size_t)j * stride;
                ok[j] = idx < total;
                if (ok[j]) v[j] = wfc[idx];
            }
#pragma unroll
            for (int j = 0; j < 4; j++) {
                if (!ok[j]) continue;
                __half h0 = __float2half_rn(v[j].x), h1 = __float2half_rn(v[j].y);
                __half h2 = __float2half_rn(v[j].z), h3 = __float2half_rn(v[j].w);
                uint32_t a = ((uint32_t)__half_as_ushort(h1) << 16) | __half_as_ushort(h0);
                uint32_t b = ((uint32_t)__half_as_ushort(h3) << 16) | __half_as_ushort(h2);
                dst[i + (size_t)j * stride] = make_uint2(a, b);
            }
        }
        return;
    }

    // ---------------- LSTM CTAs (identical to proven R14 path) ----------
    extern __shared__ char sm[];
    uint32_t sbase = smem_u32(sm);
    int tid = threadIdx.x, lane = tid & 31, wid = tid >> 5;
    int wk = wid >> 2;                     // k-group 0/1
    int ws = wid & 3;
    int wm = ws & 1, wn = ws >> 1;         // warp: 32m x 16n within group
    int bx = blockIdx.x;
    int n0 = bx * 32;                      // permuted-row base

    // ---- load resident W slice: 32 rows x 1024 k, hi+lo ----
#pragma unroll 4
    for (int r = 0; r < 16; r++) {         // hi: 4096 cp16
        int f = r * 256 + tid;
        int row = f >> 7, u = f & 127;
        cp16(sbase + (uint32_t)(row * BPITCH + u * 16),
             g_whh_hi + (size_t)(n0 + row) * KDIM + u * 8);
    }
#pragma unroll 4
    for (int r = 0; r < 16; r++) {         // lo
        int f = r * 256 + tid;
        int row = f >> 7, u = f & 127;
        cp16(sbase + (uint32_t)(B_RES + row * BPITCH + u * 16),
             g_whh_lo + (size_t)(n0 + row) * KDIM + u * 8);
    }
    cp_commit();
    cp_wait0();
    __syncthreads();

    float* gsm = (float*)(sm + AOFF);      // [2 groups][64 b][GPITCH]

    for (int t = 0; t < TSTEPS; t++) {
        float acc[2][2][4];
#pragma unroll
        for (int i = 0; i < 2; i++)
#pragma unroll
            for (int j = 0; j < 2; j++)
#pragma unroll
                for (int k = 0; k < 4; k++) acc[i][j][k] = 0.f;

        loadA_step(sbase, 0, 0, tid);
        cp_commit();

        const int NIT = 8;                 // 512 K per group / 64
        for (int it = 0; it < NIT; it++) {
            if (it + 1 < NIT) {
                loadA_step(sbase, (it + 1) & 1, it + 1, tid);
                cp_commit();
                cp_wait1();
            } else {
                cp_wait0();
            }
            __syncthreads();
            uint32_t sA = sbase + AOFF + (uint32_t)(((it & 1) * 2 + wk)) * A_STG;
#pragma unroll
            for (int kk = 0; kk < 4; kk++) {
                uint32_t a_hi[2][4], a_lo[2][4];
#pragma unroll
                for (int mt = 0; mt < 2; mt++) {
                    uint32_t arow = (uint32_t)((wm * 32 + mt * 16 + (lane & 15)) * APITCH2
                                               + kk * 32 + (lane >> 4) * 16);
                    ldsm4(a_hi[mt], sA + arow);
                    ldsm4(a_lo[mt], sA + A_HALF + arow);
                }
                uint32_t b_hi[4], b_lo[4];
                {
                    int nrow = wn * 16 + ((lane >> 4) << 3) + (lane & 7);
                    uint32_t boff = (uint32_t)(nrow * BPITCH + wk * 1024 + it * 128
                                               + kk * 32 + ((lane >> 3) & 1) * 16);
                    ldsm4(b_hi, sbase + boff);
                    ldsm4(b_lo, sbase + B_RES + boff);
                }
#pragma unroll
                for (int mt = 0; mt < 2; mt++)
#pragma unroll
                    for (int s = 0; s < 2; s++) {
                        float* c = acc[mt][s];
                        mma_bf16(c, a_hi[mt], &b_hi[s * 2]);   // hi*hi
                        mma_bf16(c, a_hi[mt], &b_lo[s * 2]);   // hi*lo
                        mma_bf16(c, a_lo[mt], &b_hi[s * 2]);   // lo*hi
                    }
            }
            __syncthreads();
        }

        // ---- dump partial gates to smem (per k-group region) ----
        float* gsmk = gsm + wk * 64 * GPITCH;
#pragma unroll
        for (int mt = 0; mt < 2; mt++) {
            int m = wm * 32 + mt * 16 + (lane >> 2);
#pragma unroll
            for (int s = 0; s < 2; s++) {
                int n = wn * 16 + s * 8 + (lane & 3) * 2;
                *(float2*)&gsmk[m * GPITCH + n] = make_float2(acc[mt][s][0], acc[mt][s][1]);
                *(float2*)&gsmk[(m + 8) * GPITCH + n] = make_float2(acc[mt][s][2], acc[mt][s][3]);
            }
        }
        __syncthreads();

        // ---- fuse: 64 b x 8 j cells (sum two k-group partials) ----
#pragma unroll
        for (int i = 0; i < 2; i++) {
            int idx = i * 256 + tid;
            int b = idx >> 3, jl = idx & 7;
            float gate[4];
#pragma unroll
            for (int gi = 0; gi < 4; gi++) {
                int nn = gi * 8 + jl;
                gate[gi] = gsm[b * GPITCH + nn]
                         + gsm[64 * GPITCH + b * GPITCH + nn]
                         + g_gate_base[(size_t)b * G4 + n0 + nn];
            }
            float iv = 1.f / (1.f + expf(-gate[0]));
            float fv = 1.f / (1.f + expf(-gate[1]));
            float gv = tanhf(gate[2]);
            float ov = 1.f / (1.f + expf(-gate[3]));
            int j  = bx * 8 + jl;
            int ci = b * HID + j;
            float c = fv * g_c[ci] + iv * gv;
            g_c[ci] = c;
            float h = ov * tanhf(c);
            __nv_bfloat16 hb = __float2bfloat16_rn(h);
            g_hhi[ci] = hb;
            g_hlo[ci] = __float2bfloat16_rn(h - __bfloat162float(hb));
            g_Ah[(size_t)(b * TSTEPS + t) * KDIM + j] = __float2half_rn(h);
        }

        // ---- grid barrier (128 LSTM CTAs only): RMW arrive, read poll ----
        if (t + 1 < TSTEPS) {
            __threadfence();
            __syncthreads();
            if (tid == 0) {
                atomicAdd(&g_bar[t], 1);
                while (*(volatile int*)&g_bar[t] < PCTA) { }
                __threadfence();
            }
            __syncthreads();
        }
    }
}

// ---- vocab GEMM: fp16 single-pass, CTA 128x128x64, 8 warps 32x64, 2 CTA/SM -
#define BN      128
#define BK      64
#define NITER   (KDIM / BK)          // 16
#define APITCH  144                  // 64k*2B + 16
#define A_T     (128 * APITCH)       // 18432
#define B_T     (128 * APITCH)       // 18432
#define STAGEB  (A_T + B_T)          // 36864
#define SMEMB   (2 * STAGEB)         // 73728 -> 2 CTAs/SM

__device__ __forceinline__ void gemm_load(uint32_t sbase, int stage, int it,
                                          int tid, int m0, int n0) {
    int kk0 = it * BK;
    uint32_t sA = sbase + (uint32_t)stage * STAGEB;
    uint32_t sB = sA + A_T;
#pragma unroll
    for (int r = 0; r < 4; r++) {           // A: 1024 cp16 (128 rows x 8)
        int f = r * 256 + tid;
        int row = f >> 3, q = f & 7;
        cp16(sA + (uint32_t)(row * APITCH + q * 16),
             g_Ah + (size_t)(m0 + row) * KDIM + kk0 + q * 8);
    }
#pragma unroll
    for (int r = 0; r < 4; r++) {           // B: 1024 cp16 (128 rows x 8)
        int f = r * 256 + tid;
        int row = f >> 3, q = f & 7;
        int n = n0 + row;
        if (n > VOCAB - 1) n = VOCAB - 1;   // clamp: results discarded
        cp16(sB + (uint32_t)(row * APITCH + q * 16),
             g_Whi + (size_t)n * KDIM + kk0 + q * 8);
    }
}

__global__ void __launch_bounds__(256, 2)
vocab_gemm_hmma(const float* __restrict__ b_fc, float* __restrict__ out) {
    extern __shared__ char sm[];
    uint32_t sbase = smem_u32(sm);
    int tid = threadIdx.x, lane = tid & 31, wid = tid >> 5;
    int wm = wid & 3, wn = wid >> 2;           // 4 m-warps x 2 n-warps, 32x64
    int m0 = blockIdx.x * 128;
    int n0 = blockIdx.y * BN;

    float acc[2][8][4];
#pragma unroll
    for (int i = 0; i < 2; i++)
#pragma unroll
        for (int j = 0; j < 8; j++)
#pragma unroll
            for (int k = 0; k < 4; k++) acc[i][j][k] = 0.f;

    gemm_load(sbase, 0, 0, tid, m0, n0);
    cp_commit();

    for (int it = 0; it < NITER; it++) {
        if (it + 1 < NITER) {
            gemm_load(sbase, (it + 1) & 1, it + 1, tid, m0, n0);
            cp_commit();
            cp_wait1();
        } else {
            cp_wait0();
        }
        __syncthreads();

        uint32_t sA = sbase + (uint32_t)(it & 1) * STAGEB;
        uint32_t sB = sA + A_T;
#pragma unroll
        for (int kk = 0; kk < 4; kk++) {
            uint32_t a[2][4];
#pragma unroll
            for (int mt = 0; mt < 2; mt++)
                ldsm4(a[mt], sA + (uint32_t)((wm * 32 + mt * 16 + (lane & 15)) * APITCH
                                             + kk * 32 + (lane >> 4) * 16));
#pragma unroll
            for (int bq = 0; bq < 4; bq++) {
                uint32_t b_hi[4];
                int nrow = wn * 64 + bq * 16 + ((lane >> 4) << 3) + (lane & 7);
                uint32_t boff = (uint32_t)(nrow * APITCH + kk * 32 + ((lane >> 3) & 1) * 16);
                ldsm4(b_hi, sB + boff);
#pragma unroll
                for (int mt = 0; mt < 2; mt++)
#pragma unroll
                    for (int s = 0; s < 2; s++)
                        mma_fp16(acc[mt][bq * 2 + s], a[mt], &b_hi[s * 2]);
            }
        }
        __syncthreads();
    }

#pragma unroll
    for (int mt = 0; mt < 2; mt++) {
        int r0 = m0 + wm * 32 + mt * 16 + (lane >> 2);
        float* o0 = out + (size_t)r0 * VOCAB;
        float* o1 = out + (size_t)(r0 + 8) * VOCAB;
#pragma unroll
        for (int nt = 0; nt < 8; nt++) {
            int col = n0 + wn * 64 + nt * 8 + (lane & 3) * 2;
            if (col < VOCAB) {
                float bz = b_fc[col];
                o0[col] = acc[mt][nt][0] + bz;
                o1[col] = acc[mt][nt][2] + bz;
            }
            if (col + 1 < VOCAB) {
                float bz = b_fc[col + 1];
                o0[col + 1] = acc[mt][nt][1] + bz;
                o1[col + 1] = acc[mt][nt][3] + bz;
            }
        }
    }
}

// ---------------------------------------------------------------------------
extern "C" void kernel_launch(void* const* d_in, const int* in_sizes, int n_in,
                              void* d_out, int out_size) {
    const float* features = (const float*)d_in[0];
    const float* W_ih     = (const float*)d_in[1];
    const float* W_hh     = (const float*)d_in[2];
    const float* b_ih     = (const float*)d_in[3];
    const float* b_hh     = (const float*)d_in[4];
    const float* W_fc     = (const float*)d_in[5];
    const float* b_fc     = (const float*)d_in[6];
    (void)in_sizes; (void)n_in; (void)out_size;

    cudaFuncSetAttribute(vocab_gemm_hmma,
                         cudaFuncAttributeMaxDynamicSharedMemorySize, SMEMB);
    cudaFuncSetAttribute(lstm_persist,
                         cudaFuncAttributeMaxDynamicSharedMemorySize, P_SMEM);

    init_kernel<<<(BATCH * HID + 255) / 256, 256>>>();
    xproj_kernel<<<128, 256>>>((const float4*)features, (const float4*)W_ih,
                               b_ih, b_hh);
    convWhh_kernel<<<G4, 256>>>((const float4*)W_hh);   // last: W_hh L2-warm

    lstm_persist<<<PCTA + CCTA, 256, P_SMEM>>>((const float4*)W_fc);

    dim3 grid(MROWS / 128, (VOCAB + BN - 1) / BN);   // (9, 393)
    vocab_gemm_hmma<<<grid, 256, SMEMB>>>(b_fc, (float*)d_out);
}

// round 17
// speedup vs baseline: 1.3801x; 1.3801x over previous
#include <cuda_runtime.h>
#include <cuda_fp16.h>
#include <cuda_bf16.h>
#include <math.h>
#include <stdint.h>

#define BATCH  64
#define EMBED  512
#define HID    1024
#define G4     4096
#define VOCAB  50257
#define TSTEPS 18
#define MROWS  (BATCH*TSTEPS)   // 1152
#define KDIM   1024
#define PCTA   128              // persistent LSTM CTAs (<=148 SMs)

// ---------------- device scratch (static device globals; no allocs) ---------
__device__ float g_gate_base[BATCH * G4];            // [b][p]  (permuted rows)
__device__ float g_c[BATCH * HID];                   // [b][j]
__device__ int   g_bar[TSTEPS];                      // grid-barrier counters
__device__ __half g_hf[BATCH * HID];                 // h fp16 [b][j]
__device__ __half g_whh_hi[G4 * KDIM];               // permuted rows, 8 MB
__device__ __half g_whh_lo[G4 * KDIM];               // 8 MB (fp16 residual)
__device__ __half g_Ah[MROWS * KDIM];                // vocab A fp16  2.3 MB
__device__ __half g_Whi[(size_t)VOCAB * KDIM];       // 103 MB

// permuted row: r = gi*HID + j  ->  p = (j>>3)*32 + gi*8 + (j&7)
__device__ __forceinline__ int perm_row(int r) {
    int gi = r >> 10, j = r & (HID - 1);
    return ((j >> 3) << 5) + (gi << 3) + (j & 7);
}

// ---------------------------------------------------------------- helpers ---
__device__ __forceinline__ uint32_t smem_u32(const void* p) {
    uint32_t a;
    asm("{ .reg .u64 t; cvta.to.shared.u64 t, %1; cvt.u32.u64 %0, t; }"
        : "=r"(a) : "l"(p));
    return a;
}
__device__ __forceinline__ void cp16(uint32_t s, const void* g) {
    asm volatile("cp.async.cg.shared.global [%0], [%1], 16;" :: "r"(s), "l"(g) : "memory");
}
__device__ __forceinline__ void cp_commit() {
    asm volatile("cp.async.commit_group;" ::: "memory");
}
__device__ __forceinline__ void cp_wait1() {
    asm volatile("cp.async.wait_group 1;" ::: "memory");
}
__device__ __forceinline__ void cp_wait0() {
    asm volatile("cp.async.wait_group 0;" ::: "memory");
}
__device__ __forceinline__ void ldsm4(uint32_t* r, uint32_t a) {
    asm volatile("ldmatrix.sync.aligned.m8n8.x4.shared.b16 {%0,%1,%2,%3}, [%4];"
                 : "=r"(r[0]), "=r"(r[1]), "=r"(r[2]), "=r"(r[3]) : "r"(a));
}
__device__ __forceinline__ void mma_fp16(float* c, const uint32_t* a, const uint32_t* b) {
    asm volatile(
        "mma.sync.aligned.m16n8k16.row.col.f32.f16.f16.f32 "
        "{%0,%1,%2,%3},{%4,%5,%6,%7},{%8,%9},{%0,%1,%2,%3};"
        : "+f"(c[0]), "+f"(c[1]), "+f"(c[2]), "+f"(c[3])
        : "r"(a[0]), "r"(a[1]), "r"(a[2]), "r"(a[3]), "r"(b[0]), "r"(b[1]));
}

// ---------------------------------------------------------------- init ------
__global__ void init_kernel() {
    int i = blockIdx.x * blockDim.x + threadIdx.x;
    if (i < BATCH * HID) {
        g_c[i] = 0.f;
        g_hf[i] = __float2half(0.f);
    }
    if (i < TSTEPS) g_bar[i] = 0;
}

// --------------------------------- x_proj -> gate_base[b][perm(r)] ----------
__global__ void xproj_kernel(const float4* __restrict__ feat4,
                             const float4* __restrict__ wih4,
                             const float*  __restrict__ b_ih,
                             const float*  __restrict__ b_hh) {
    __shared__ float4 fs[BATCH * 32];
    int tid = threadIdx.x;
    int rl  = tid & 31;
    int bg  = tid >> 5;
    int r   = blockIdx.x * 32 + rl;
    float acc[8];
#pragma unroll
    for (int j = 0; j < 8; j++) acc[j] = 0.f;
    for (int ec = 0; ec < 4; ec++) {
        __syncthreads();
#pragma unroll
        for (int i = 0; i < 8; i++) {
            int lin = i * 256 + tid;
            int b = lin >> 5, q = lin & 31;
            fs[lin] = feat4[b * 128 + ec * 32 + q];
        }
        __syncthreads();
#pragma unroll 4
        for (int eq = 0; eq < 32; eq++) {
            float4 w = wih4[r * 128 + ec * 32 + eq];
#pragma unroll
            for (int jj = 0; jj < 8; jj++) {
                float4 f = fs[(bg * 8 + jj) * 32 + eq];
                acc[jj] += w.x * f.x + w.y * f.y + w.z * f.z + w.w * f.w;
            }
        }
    }
    float bias = b_ih[r] + b_hh[r];
    int p = perm_row(r);
#pragma unroll
    for (int jj = 0; jj < 8; jj++)
        g_gate_base[(bg * 8 + jj) * G4 + p] = acc[jj] + bias;
}

// --------------------------- W_fc fp32 -> fp16, coalesced, MLP=4 ------------
__global__ void convW_kernel(const float4* __restrict__ w) {
    const size_t total = (size_t)VOCAB * 256;     // float4 count
    size_t b0 = (size_t)blockIdx.x * 1024 + threadIdx.x;
    float4 v[4];
    bool ok[4];
#pragma unroll
    for (int i = 0; i < 4; i++) {                 // 4 coalesced loads in flight
        size_t idx = b0 + (size_t)i * 256;
        ok[i] = idx < total;
        if (ok[i]) v[i] = w[idx];
    }
    uint2* dst = (uint2*)g_Whi;
#pragma unroll
    for (int i = 0; i < 4; i++) {
        if (!ok[i]) continue;
        __half h0 = __float2half_rn(v[i].x), h1 = __float2half_rn(v[i].y);
        __half h2 = __float2half_rn(v[i].z), h3 = __float2half_rn(v[i].w);
        uint32_t a = ((uint32_t)__half_as_ushort(h1) << 16) | __half_as_ushort(h0);
        uint32_t b = ((uint32_t)__half_as_ushort(h3) << 16) | __half_as_ushort(h2);
        dst[b0 + (size_t)i * 256] = make_uint2(a, b);
    }
}

// ----------------------- W_hh fp32 -> fp16 hi/lo, permuted rows -------------
__global__ void convWhh_kernel(const float4* __restrict__ w) {
    int r = blockIdx.x;              // source row 0..4095
    int q = threadIdx.x;             // 0..255
    float4 v = w[(size_t)r * 256 + q];
    float x[4] = {v.x, v.y, v.z, v.w};
    __half hi[4], lo[4];
#pragma unroll
    for (int j = 0; j < 4; j++) {
        hi[j] = __float2half_rn(x[j]);
        lo[j] = __float2half_rn(x[j] - __half2float(hi[j]));
    }
    uint32_t h01 = ((uint32_t)__half_as_ushort(hi[1]) << 16) | __half_as_ushort(hi[0]);
    uint32_t h23 = ((uint32_t)__half_as_ushort(hi[3]) << 16) | __half_as_ushort(hi[2]);
    uint32_t l01 = ((uint32_t)__half_as_ushort(lo[1]) << 16) | __half_as_ushort(lo[0]);
    uint32_t l23 = ((uint32_t)__half_as_ushort(lo[3]) << 16) | __half_as_ushort(lo[2]);
    int p = perm_row(r);
    ((uint2*)(g_whh_hi + (size_t)p * KDIM))[q] = make_uint2(h01, h23);
    ((uint2*)(g_whh_lo + (size_t)p * KDIM))[q] = make_uint2(l01, l23);
}

// -------------------- persistent LSTM: 18 steps, 1 launch -------------------
// 128 CTAs x 256 thr (8 warps = 2 k-groups x 4 warps). CTA bx owns permuted
// rows [bx*32, bx*32+32). W_hh (fp16 hi/lo) resident in smem; A = h fp16
// streams per step. 2-pass mma: A*Whi + A*Wlo.
#define BPITCH  2064                  // 1024k*2B + 16
#define B_RES   (32 * BPITCH)         // 66048 per half
#define AOFF    (2 * B_RES)           // 132096
#define APITCH2 144                   // 64k*2B + 16
#define A_STG   (64 * APITCH2)        // 9216 (per group per stage, hi only)
#define P_SMEM  (AOFF + 4 * A_STG)    // 168960
#define GPITCH  34                    // EVEN: float2 stores stay 8B-aligned

__device__ __forceinline__ void loadA_step(uint32_t sbase, int stage, int it,
                                           int tid) {
#pragma unroll
    for (int r = 0; r < 4; r++) {          // 1024 cp16: 2 groups, fp16 A
        int f = r * 256 + tid;
        int g = f >> 9, q = f & 511;
        int row = q >> 3, qq = q & 7;
        int k0 = g * 512 + it * 64;
        cp16(sbase + AOFF + (uint32_t)(stage * 2 + g) * A_STG
             + (uint32_t)(row * APITCH2 + qq * 16),
             g_hf + (size_t)row * KDIM + k0 + qq * 8);
    }
}

__global__ void __launch_bounds__(256)
lstm_persist() {
    extern __shared__ char sm[];
    uint32_t sbase = smem_u32(sm);
    int tid = threadIdx.x, lane = tid & 31, wid = tid >> 5;
    int wk = wid >> 2;                     // k-group 0/1
    int ws = wid & 3;
    int wm = ws & 1, wn = ws >> 1;         // warp: 32m x 16n within group
    int bx = blockIdx.x;
    int n0 = bx * 32;                      // permuted-row base

    // ---- load resident W slice: 32 rows x 1024 k, hi+lo ----
#pragma unroll 4
    for (int r = 0; r < 16; r++) {         // hi: 4096 cp16
        int f = r * 256 + tid;
        int row = f >> 7, u = f & 127;
        cp16(sbase + (uint32_t)(row * BPITCH + u * 16),
             g_whh_hi + (size_t)(n0 + row) * KDIM + u * 8);
    }
#pragma unroll 4
    for (int r = 0; r < 16; r++) {         // lo
        int f = r * 256 + tid;
        int row = f >> 7, u = f & 127;
        cp16(sbase + (uint32_t)(B_RES + row * BPITCH + u * 16),
             g_whh_lo + (size_t)(n0 + row) * KDIM + u * 8);
    }
    cp_commit();
    cp_wait0();
    __syncthreads();

    float* gsm = (float*)(sm + AOFF);      // [2 groups][64 b][GPITCH]

    for (int t = 0; t < TSTEPS; t++) {
        float acc[2][2][4];
#pragma unroll
        for (int i = 0; i < 2; i++)
#pragma unroll
            for (int j = 0; j < 2; j++)
#pragma unroll
                for (int k = 0; k < 4; k++) acc[i][j][k] = 0.f;

        loadA_step(sbase, 0, 0, tid);
        cp_commit();

        const int NIT = 8;                 // 512 K per group / 64
        for (int it = 0; it < NIT; it++) {
            if (it + 1 < NIT) {
                loadA_step(sbase, (it + 1) & 1, it + 1, tid);
                cp_commit();
                cp_wait1();
            } else {
                cp_wait0();
            }
            __syncthreads();
            uint32_t sA = sbase + AOFF + (uint32_t)(((it & 1) * 2 + wk)) * A_STG;
#pragma unroll
            for (int kk = 0; kk < 4; kk++) {
                uint32_t a[2][4];
#pragma unroll
                for (int mt = 0; mt < 2; mt++) {
                    uint32_t arow = (uint32_t)((wm * 32 + mt * 16 + (lane & 15)) * APITCH2
                                               + kk * 32 + (lane >> 4) * 16);
                    ldsm4(a[mt], sA + arow);
                }
                uint32_t b_hi[4], b_lo[4];
                {
                    int nrow = wn * 16 + ((lane >> 4) << 3) + (lane & 7);
                    uint32_t boff = (uint32_t)(nrow * BPITCH + wk * 1024 + it * 128
                                               + kk * 32 + ((lane >> 3) & 1) * 16);
                    ldsm4(b_hi, sbase + boff);
                    ldsm4(b_lo, sbase + B_RES + boff);
                }
#pragma unroll
                for (int mt = 0; mt < 2; mt++)
#pragma unroll
                    for (int s = 0; s < 2; s++) {
                        float* c = acc[mt][s];
                        mma_fp16(c, a[mt], &b_hi[s * 2]);   // A * Whi
                        mma_fp16(c, a[mt], &b_lo[s * 2]);   // A * Wlo
                    }
            }
            __syncthreads();
        }

        // ---- dump partial gates to smem (per k-group region) ----
        float* gsmk = gsm + wk * 64 * GPITCH;
#pragma unroll
        for (int mt = 0; mt < 2; mt++) {
            int m = wm * 32 + mt * 16 + (lane >> 2);
#pragma unroll
            for (int s = 0; s < 2; s++) {
                int n = wn * 16 + s * 8 + (lane & 3) * 2;
                *(float2*)&gsmk[m * GPITCH + n] = make_float2(acc[mt][s][0], acc[mt][s][1]);
                *(float2*)&gsmk[(m + 8) * GPITCH + n] = make_float2(acc[mt][s][2], acc[mt][s][3]);
            }
        }
        __syncthreads();

        // ---- fuse: 64 b x 8 j cells (sum two k-group partials) ----
#pragma unroll
        for (int i = 0; i < 2; i++) {
            int idx = i * 256 + tid;
            int b = idx >> 3, jl = idx & 7;
            float gate[4];
#pragma unroll
            for (int gi = 0; gi < 4; gi++) {
                int nn = gi * 8 + jl;
                gate[gi] = gsm[b * GPITCH + nn]
                         + gsm[64 * GPITCH + b * GPITCH + nn]
                         + g_gate_base[(size_t)b * G4 + n0 + nn];
            }
            float iv = 1.f / (1.f + expf(-gate[0]));
            float fv = 1.f / (1.f + expf(-gate[1]));
            float gv = tanhf(gate[2]);
            float ov = 1.f / (1.f + expf(-gate[3]));
            int j  = bx * 8 + jl;
            int ci = b * HID + j;
            float c = fv * g_c[ci] + iv * gv;
            g_c[ci] = c;
            float h = ov * tanhf(c);
            __half hf = __float2half_rn(h);
            g_hf[ci] = hf;
            g_Ah[(size_t)(b * TSTEPS + t) * KDIM + j] = hf;
        }

        // ---- grid barrier: RMW arrive, read-only poll ----
        if (t + 1 < TSTEPS) {
            __threadfence();
            __syncthreads();
            if (tid == 0) {
                atomicAdd(&g_bar[t], 1);
                while (*(volatile int*)&g_bar[t] < PCTA) { }
                __threadfence();
            }
            __syncthreads();
        }
    }
}

// ---- vocab GEMM: fp16 single-pass, CTA 128x128x64, 8 warps 32x64, 2 CTA/SM -
#define BN      128
#define BK      64
#define NITER   (KDIM / BK)          // 16
#define APITCH  144                  // 64k*2B + 16
#define A_T     (128 * APITCH)       // 18432
#define B_T     (128 * APITCH)       // 18432
#define STAGEB  (A_T + B_T)          // 36864
#define SMEMB   (2 * STAGEB)         // 73728 -> 2 CTAs/SM

__device__ __forceinline__ void gemm_load(uint32_t sbase, int stage, int it,
                                          int tid, int m0, int n0) {
    int kk0 = it * BK;
    uint32_t sA = sbase + (uint32_t)stage * STAGEB;
    uint32_t sB = sA + A_T;
#pragma unroll
    for (int r = 0; r < 4; r++) {           // A: 1024 cp16 (128 rows x 8)
        int f = r * 256 + tid;
        int row = f >> 3, q = f & 7;
        cp16(sA + (uint32_t)(row * APITCH + q * 16),
             g_Ah + (size_t)(m0 + row) * KDIM + kk0 + q * 8);
    }
#pragma unroll
    for (int r = 0; r < 4; r++) {           // B: 1024 cp16 (128 rows x 8)
        int f = r * 256 + tid;
        int row = f >> 3, q = f & 7;
        int n = n0 + row;
        if (n > VOCAB - 1) n = VOCAB - 1;   // clamp: results discarded
        cp16(sB + (uint32_t)(row * APITCH + q * 16),
             g_Whi + (size_t)n * KDIM + kk0 + q * 8);
    }
}

__global__ void __launch_bounds__(256, 2)
vocab_gemm_hmma(const float* __restrict__ b_fc, float* __restrict__ out) {
    extern __shared__ char sm[];
    uint32_t sbase = smem_u32(sm);
    int tid = threadIdx.x, lane = tid & 31, wid = tid >> 5;
    int wm = wid & 3, wn = wid >> 2;           // 4 m-warps x 2 n-warps, 32x64
    int m0 = blockIdx.x * 128;
    int n0 = blockIdx.y * BN;

    float acc[2][8][4];
#pragma unroll
    for (int i = 0; i < 2; i++)
#pragma unroll
        for (int j = 0; j < 8; j++)
#pragma unroll
            for (int k = 0; k < 4; k++) acc[i][j][k] = 0.f;

    gemm_load(sbase, 0, 0, tid, m0, n0);
    cp_commit();

    for (int it = 0; it < NITER; it++) {
        if (it + 1 < NITER) {
            gemm_load(sbase, (it + 1) & 1, it + 1, tid, m0, n0);
            cp_commit();
            cp_wait1();
        } else {
            cp_wait0();
        }
        __syncthreads();

        uint32_t sA = sbase + (uint32_t)(it & 1) * STAGEB;
        uint32_t sB = sA + A_T;
#pragma unroll
        for (int kk = 0; kk < 4; kk++) {
            uint32_t a[2][4];
#pragma unroll
            for (int mt = 0; mt < 2; mt++)
                ldsm4(a[mt], sA + (uint32_t)((wm * 32 + mt * 16 + (lane & 15)) * APITCH
                                             + kk * 32 + (lane >> 4) * 16));
#pragma unroll
            for (int bq = 0; bq < 4; bq++) {
                uint32_t b_hi[4];
                int nrow = wn * 64 + bq * 16 + ((lane >> 4) << 3) + (lane & 7);
                uint32_t boff = (uint32_t)(nrow * APITCH + kk * 32 + ((lane >> 3) & 1) * 16);
                ldsm4(b_hi, sB + boff);
#pragma unroll
                for (int mt = 0; mt < 2; mt++)
#pragma unroll
                    for (int s = 0; s < 2; s++)
                        mma_fp16(acc[mt][bq * 2 + s], a[mt], &b_hi[s * 2]);
            }
        }
        __syncthreads();
    }

#pragma unroll
    for (int mt = 0; mt < 2; mt++) {
        int r0 = m0 + wm * 32 + mt * 16 + (lane >> 2);
        float* o0 = out + (size_t)r0 * VOCAB;
        float* o1 = out + (size_t)(r0 + 8) * VOCAB;
#pragma unroll
        for (int nt = 0; nt < 8; nt++) {
            int col = n0 + wn * 64 + nt * 8 + (lane & 3) * 2;
            if (col < VOCAB) {
                float bz = b_fc[col];
                o0[col] = acc[mt][nt][0] + bz;
                o1[col] = acc[mt][nt][2] + bz;
            }
            if (col + 1 < VOCAB) {
                float bz = b_fc[col + 1];
                o0[col + 1] = acc[mt][nt][1] + bz;
                o1[col + 1] = acc[mt][nt][3] + bz;
            }
        }
    }
}

// ---------------------------------------------------------------------------
extern "C" void kernel_launch(void* const* d_in, const int* in_sizes, int n_in,
                              void* d_out, int out_size) {
    const float* features = (const float*)d_in[0];
    const float* W_ih     = (const float*)d_in[1];
    const float* W_hh     = (const float*)d_in[2];
    const float* b_ih     = (const float*)d_in[3];
    const float* b_hh     = (const float*)d_in[4];
    const float* W_fc     = (const float*)d_in[5];
    const float* b_fc     = (const float*)d_in[6];
    (void)in_sizes; (void)n_in; (void)out_size;

    cudaFuncSetAttribute(vocab_gemm_hmma,
                         cudaFuncAttributeMaxDynamicSharedMemorySize, SMEMB);
    cudaFuncSetAttribute(lstm_persist,
                         cudaFuncAttributeMaxDynamicSharedMemorySize, P_SMEM);

    init_kernel<<<(BATCH * HID + 255) / 256, 256>>>();
    xproj_kernel<<<128, 256>>>((const float4*)features, (const float4*)W_ih,
                               b_ih, b_hh);
    {   // convW: VOCAB*256 float4 total, 1024 per block
        size_t total = (size_t)VOCAB * 256;
        int blocks = (int)((total + 1023) / 1024);
        convW_kernel<<<blocks, 256>>>((const float4*)W_fc);
    }
    convWhh_kernel<<<G4, 256>>>((const float4*)W_hh);   // last: W_hh L2-warm

    lstm_persist<<<PCTA, 256, P_SMEM>>>();

    dim3 grid(MROWS / 128, (VOCAB + BN - 1) / BN);   // (9, 393)
    vocab_gemm_hmma<<<grid, 256, SMEMB>>>(b_fc, (float*)d_out);
}